// round 15
// baseline (speedup 1.0000x reference)
#include <cuda_runtime.h>
#include <cuda_bf16.h>
#include <cstdint>

#define T_STEPS 512
#define BATCH   64
#define IDIM    256
#define HDIM    512
#define NCTA    128
#define NTHR2   512
#define JCOL    4
#define GR      16
#define HROWP   264            // bf16 per padded A row (528 B)
#define USTR    520            // bf16 per padded U row, K=512 (1040 B)
#define XROWP   264            // bf16 per padded x-tile row, K=256 (528 B)

typedef unsigned long long ull;

// ---- persistent device scratch ----
__device__ float g_xw[(size_t)T_STEPS * NCTA * GR * BATCH];     // [t][jg][row16][b]
__device__ __nv_bfloat16 g_xa[(size_t)T_STEPS * 128 * XROWP];   // per-t A tiles (hi 0-63, lo 64-127)
__device__ __nv_bfloat16 g_ha[2][2][128 * HROWP];               // [buf][khalf][row128 x HROWP]
__device__ unsigned int g_flags[NCTA * 32];                     // 128B-padded per-CTA flags

// ---------------- helpers ----------------
__device__ __forceinline__ float sigmoidf_(float v) {
    return __fdividef(1.0f, 1.0f + __expf(-v));
}
__device__ __forceinline__ float tanhfast_(float v) {
    return 1.0f - __fdividef(2.0f, __expf(2.0f * v) + 1.0f);
}
__device__ __forceinline__ unsigned ld_acquire_gpu(const unsigned* p) {
    unsigned v;
    asm volatile("ld.acquire.gpu.u32 %0, [%1];" : "=r"(v) : "l"(p) : "memory");
    return v;
}
__device__ __forceinline__ void st_release_gpu(unsigned* p, unsigned v) {
    asm volatile("st.release.gpu.u32 [%0], %1;" :: "l"(p), "r"(v) : "memory");
}
__device__ __forceinline__ uint32_t smem_u32(const void* p) {
    uint32_t a;
    asm("{ .reg .u64 t; cvta.to.shared.u64 t, %1; cvt.u32.u64 %0, t; }" : "=r"(a) : "l"(p));
    return a;
}
__device__ __forceinline__ void bulkcp(uint32_t dst, const void* src, uint32_t bytes,
                                       uint32_t mbar) {
    asm volatile(
        "cp.async.bulk.shared::cluster.global.mbarrier::complete_tx::bytes [%0], [%1], %2, [%3];"
        :: "r"(dst), "l"(src), "r"(bytes), "r"(mbar) : "memory");
}
#define MBARRIER_INIT(mb, c) \
    asm volatile("mbarrier.init.shared.b64 [%0], %1;" :: "r"((uint32_t)(mb)), "r"((uint32_t)(c)) : "memory")
#define MBARRIER_EXPECT_TX(mb, tx) \
    asm volatile("mbarrier.arrive.expect_tx.shared.b64 _, [%0], %1;" \
        :: "r"((uint32_t)(mb)), "r"((uint32_t)(tx)) : "memory")
#define MBARRIER_WAIT_PARITY(mb, par) do {                                            \
    uint32_t _mb = (uint32_t)(mb); uint32_t _p = (uint32_t)(par); uint32_t _done;     \
    asm volatile("{\n\t.reg .pred p;\n\t"                                             \
        "mbarrier.try_wait.parity.acquire.cta.shared::cta.b64 p, [%1], %2;\n\t"       \
        "selp.b32 %0, 1, 0, p;\n\t}" : "=r"(_done) : "r"(_mb), "r"(_p) : "memory");   \
    if (!_done) {                                                                     \
        asm volatile("{\n\t.reg .pred P1;\n\t"                                        \
            "WL_%=:\n\t"                                                              \
            "mbarrier.try_wait.parity.acquire.cta.shared::cta.b64 P1, [%0], %1, 0x989680;\n\t" \
            "@P1 bra.uni WD_%=;\n\t"                                                  \
            "bra.uni WL_%=;\n\t"                                                      \
            "WD_%=:\n\t}" :: "r"(_mb), "r"(_p) : "memory");                           \
    }                                                                                 \
} while (0)

#define LDMX4(r0, r1, r2, r3, addr) \
    asm volatile("ldmatrix.sync.aligned.m8n8.x4.shared.b16 {%0,%1,%2,%3}, [%4];" \
        : "=r"(r0), "=r"(r1), "=r"(r2), "=r"(r3) : "r"(addr))
#define LDMX2(r0, r1, addr) \
    asm volatile("ldmatrix.sync.aligned.m8n8.x2.shared.b16 {%0,%1}, [%2];" \
        : "=r"(r0), "=r"(r1) : "r"(addr))
#define MMA16816(d0, d1, d2, d3, a0, a1, a2, a3, b0, b1) \
    asm volatile("mma.sync.aligned.m16n8k16.row.col.f32.bf16.bf16.f32 " \
        "{%0,%1,%2,%3}, {%4,%5,%6,%7}, {%8,%9}, {%0,%1,%2,%3};" \
        : "+f"(d0), "+f"(d1), "+f"(d2), "+f"(d3) \
        : "r"(a0), "r"(a1), "r"(a2), "r"(a3), "r"(b0), "r"(b1))

// ============================================================================
// Kernel 0: convert x -> g_xa (bf16 hi/lo, padded per-t A tiles)  [R13 verbatim]
// ============================================================================
__global__ void __launch_bounds__(256, 4)
lstm_xcvt_kernel(const float* __restrict__ x)
{
    const int tid = blockIdx.x * 256 + threadIdx.x;
    #pragma unroll
    for (int i = 0; i < 4; ++i) {
        int item = tid + i * 524288;
        int t  = item >> 12;
        int rm = item & 4095;
        int b  = rm >> 6;
        int kq = rm & 63;
        float4 v = __ldg(reinterpret_cast<const float4*>(
            x + ((size_t)t * BATCH + b) * IDIM + kq * 4));
        float h0 = __bfloat162float(__float2bfloat16_rn(v.x));
        float h1 = __bfloat162float(__float2bfloat16_rn(v.y));
        float h2 = __bfloat162float(__float2bfloat16_rn(v.z));
        float h3 = __bfloat162float(__float2bfloat16_rn(v.w));
        uint32_t hp0, hp1, lp0, lp1;
        asm("cvt.rn.bf16x2.f32 %0, %1, %2;" : "=r"(hp0) : "f"(h1), "f"(h0));
        asm("cvt.rn.bf16x2.f32 %0, %1, %2;" : "=r"(hp1) : "f"(h3), "f"(h2));
        asm("cvt.rn.bf16x2.f32 %0, %1, %2;" : "=r"(lp0) : "f"(v.y - h1), "f"(v.x - h0));
        asm("cvt.rn.bf16x2.f32 %0, %1, %2;" : "=r"(lp1) : "f"(v.w - h3), "f"(v.z - h2));
        __nv_bfloat16* dst = g_xa + (size_t)t * 128 * XROWP;
        uint2 hw; hw.x = hp0; hw.y = hp1;
        uint2 lw; lw.x = lp0; lw.y = lp1;
        *reinterpret_cast<uint2*>(dst + b * XROWP + kq * 4) = hw;
        *reinterpret_cast<uint2*>(dst + (b + 64) * XROWP + kq * 4) = lw;
    }
}

// ============================================================================
// Kernel 1: phase-1 mma (double-buffered, gsm overlays dead A buffer) [R13 verbatim]
// ============================================================================
#define P1_TT    32
#define XA_BYTES (128 * XROWP * 2)       // 67584
#define WSTRB    (XROWP * 2)             // 528 B per W row (K=256)

#define Q_MB0   0
#define Q_MB1   8
#define Q_BS    64
#define Q_W     1024
#define Q_A0    68608
#define Q_A1    136192
#define Q_TOTAL 203776

__global__ void __launch_bounds__(NTHR2, 1)
lstm_xw_kernel(const float* __restrict__ Wf, const float* __restrict__ bWf,
               const float* __restrict__ Wi, const float* __restrict__ bWi,
               const float* __restrict__ Wo, const float* __restrict__ bWo,
               const float* __restrict__ Wc, const float* __restrict__ bWc,
               const float* __restrict__ bUf, const float* __restrict__ bUi,
               const float* __restrict__ bUo, const float* __restrict__ bUc)
{
    extern __shared__ char smem[];
    const uint32_t smu = smem_u32(smem);
    float* bsm = (float*)(smem + Q_BS);

    const int tid  = threadIdx.x;
    const int wid  = tid >> 5;
    const int lane = tid & 31;
    const int jg   = blockIdx.x;
    const int t0   = blockIdx.y * P1_TT;
    const int mt   = wid & 7;
    const int ng   = wid >> 3;

    if (tid == 0) {
        MBARRIER_INIT(smu + Q_MB0, 1);
        MBARRIER_INIT(smu + Q_MB1, 1);
    }
    {
        const float* Wg[4]  = {Wf, Wi, Wo, Wc};
        const float* bWg[4] = {bWf, bWi, bWo, bWc};
        const float* bUg[4] = {bUf, bUi, bUo, bUc};
        #pragma unroll 4
        for (int i = 0; i < 32; ++i) {
            int idx = tid + i * NTHR2;
            int row = idx >> 8;
            int k   = idx & 255;
            int gate = (row >> 2) & 3;
            int jcol = jg * 16 + (row >> 4) * 4 + (row & 3);
            float f = Wg[gate][jcol * IDIM + k];
            __nv_bfloat16 hi = __float2bfloat16_rn(f);
            __nv_bfloat16 lo = __float2bfloat16_rn(f - __bfloat162float(hi));
            *(__nv_bfloat16*)(smem + Q_W + row * WSTRB + k * 2) = hi;
            *(__nv_bfloat16*)(smem + Q_W + 64 * WSTRB + row * WSTRB + k * 2) = lo;
        }
        if (tid < 64) {
            int gate = (tid >> 2) & 3;
            int jcol = jg * 16 + (tid >> 4) * 4 + (tid & 3);
            bsm[tid] = (float)(bWg[gate][jcol] + bUg[gate][jcol]);
        }
    }
    __syncthreads();
    if (tid == 0) {
        MBARRIER_EXPECT_TX(smu + Q_MB0, XA_BYTES);
        bulkcp(smu + Q_A0, g_xa + (size_t)t0 * 128 * XROWP, XA_BYTES, smu + Q_MB0);
    }

    const uint32_t a_lane = (uint32_t)(lane & 15) * WSTRB + (uint32_t)((lane >> 4) << 4);
    const uint32_t b_lane = (uint32_t)(lane & 7) * WSTRB + (uint32_t)(((lane >> 3) & 1) << 4);

    for (int tt = 0; tt < P1_TT; ++tt) {
        const int t   = t0 + tt;
        const int cur = tt & 1;
        const uint32_t Acur = smu + (cur ? Q_A1 : Q_A0);

        if (tid == 0 && tt + 1 < P1_TT) {
            const uint32_t mbn = smu + ((tt + 1) & 1 ? Q_MB1 : Q_MB0);
            MBARRIER_EXPECT_TX(mbn, XA_BYTES);
            bulkcp(smu + ((tt + 1) & 1 ? Q_A1 : Q_A0),
                   g_xa + (size_t)(t + 1) * 128 * XROWP, XA_BYTES, mbn);
        }

        MBARRIER_WAIT_PARITY(smu + (cur ? Q_MB1 : Q_MB0), (tt >> 1) & 1);

        float d0[4], d1[4], d2[4], d3[4];
        #pragma unroll
        for (int q = 0; q < 4; ++q) { d0[q] = d1[q] = d2[q] = d3[q] = 0.f; }

        const uint32_t abase = Acur + (uint32_t)mt * 16 * WSTRB + a_lane;
        #pragma unroll
        for (int k = 0; k < 16; ++k) {
            uint32_t a0, a1, a2, a3;
            LDMX4(a0, a1, a2, a3, abase + (uint32_t)k * 32);
            #pragma unroll
            for (int q = 0; q < 4; ++q) {
                uint32_t bh = smu + Q_W + (uint32_t)(ng * 32 + q * 8) * WSTRB + b_lane
                            + (uint32_t)k * 32;
                uint32_t b0, b1;
                LDMX2(b0, b1, bh);
                MMA16816(d0[q], d1[q], d2[q], d3[q], a0, a1, a2, a3, b0, b1);
                LDMX2(b0, b1, bh + 64 * WSTRB);
                MMA16816(d0[q], d1[q], d2[q], d3[q], a0, a1, a2, a3, b0, b1);
            }
        }

        __syncthreads();
        float* gsm = (float*)(smem + (cur ? Q_A1 : Q_A0));
        {
            int m = mt * 16 + (lane >> 2);
            #pragma unroll
            for (int q = 0; q < 4; ++q) {
                int n = ng * 32 + q * 8 + 2 * (lane & 3);
                gsm[m * 66 + n]           = d0[q];
                gsm[m * 66 + n + 1]       = d1[q];
                gsm[(m + 8) * 66 + n]     = d2[q];
                gsm[(m + 8) * 66 + n + 1] = d3[q];
            }
        }
        __syncthreads();
        #pragma unroll
        for (int i = 0; i < 2; ++i) {
            int oidx = tid + i * NTHR2;
            int n  = oidx >> 4;
            int b4 = (oidx & 15) * 4;
            float bb = bsm[n];
            float4 o;
            o.x = gsm[(b4 + 0) * 66 + n] + gsm[(b4 + 64) * 66 + n] + bb;
            o.y = gsm[(b4 + 1) * 66 + n] + gsm[(b4 + 65) * 66 + n] + bb;
            o.z = gsm[(b4 + 2) * 66 + n] + gsm[(b4 + 66) * 66 + n] + bb;
            o.w = gsm[(b4 + 3) * 66 + n] + gsm[(b4 + 67) * 66 + n] + bb;
            size_t row128 = (size_t)t * NCTA + 4 * jg + (n >> 4);
            *reinterpret_cast<float4*>(
                g_xw + (row128 * GR + (n & 15)) * BATCH + b4) = o;
        }
        __syncthreads();
    }
}

// ============================================================================
// Phase 2: 128 CTAs x 4 h-cols, mma.sync (DUAL accumulator chains),
// warp-specialized poller + split flags [R14 structure].
// ============================================================================
#define ACHUNK_BYTES (128 * HROWP * 2)        // 67584
#define XW_BYTES     (GR * BATCH * 4)         // 4096

#define RB_MB0   0
#define RB_MB1   8
#define RB_MBX   16
#define RB_EB    24
#define RB_XW    64
#define RB_GSM   (RB_XW + 2 * XW_BYTES)       // 8256; gsm 128*20*4 = 10240
#define RB_U     (RB_GSM + 10240)             // hi 16*1040 + lo 16*1040 = 33280
#define RB_A     (RB_U + 33280)               // 2 * 67584 = 135168
#define RB_TOTAL (RB_A + 2 * ACHUNK_BYTES)    // 186944

__global__ void __launch_bounds__(NTHR2, 1)
lstm_recur_kernel(const float* __restrict__ Uf, const float* __restrict__ Ui,
                  const float* __restrict__ Uo, const float* __restrict__ Uc,
                  float* __restrict__ out)
{
    extern __shared__ char smem[];
    const uint32_t smu = smem_u32(smem);
    float* xwf = (float*)(smem + RB_XW);
    float* gsm = (float*)(smem + RB_GSM);

    const int tid  = threadIdx.x;
    const int wid  = tid >> 5;
    const int lane = tid & 31;
    const int bx   = blockIdx.x;
    const int j0   = bx * JCOL;
    const int mt   = wid & 7;
    const int nt   = wid >> 3;

    if (tid == 0) {
        MBARRIER_INIT(smu + RB_MB0, 1);
        MBARRIER_INIT(smu + RB_MB1, 1);
        MBARRIER_INIT(smu + RB_MBX, 1);
        *(unsigned*)(smem + RB_EB) = ld_acquire_gpu(&g_flags[bx * 32]);
    }
    {
        const float* Ug[4] = {Uf, Ui, Uo, Uc};
        for (int i = 0; i < 16; ++i) {
            int idx = tid + i * NTHR2;
            int row = idx >> 9;
            int k   = idx & 511;
            float f = Ug[row >> 2][(j0 + (row & 3)) * HDIM + k];
            __nv_bfloat16 hi = __float2bfloat16_rn(f);
            __nv_bfloat16 lo = __float2bfloat16_rn(f - __bfloat162float(hi));
            *(__nv_bfloat16*)(smem + RB_U + (row * USTR + k) * 2) = hi;
            *(__nv_bfloat16*)(smem + RB_U + 16 * USTR * 2 + (row * USTR + k) * 2) = lo;
        }
        if (tid < 256) {
            const float* src = g_xw + (size_t)bx * GR * BATCH;
            float4 v = __ldg(reinterpret_cast<const float4*>(src + tid * 4));
            *reinterpret_cast<float4*>(xwf + tid * 4) = v;
        }
    }
    __syncthreads();
    const unsigned base = *(unsigned*)(smem + RB_EB);

    float* hseq = out;
    float* hfin = out + (size_t)T_STEPS * BATCH * HDIM;
    float* cfin = hfin + BATCH * HDIM;

    const uint32_t a_lane = (uint32_t)(lane & 15) * (HROWP * 2) + (uint32_t)((lane >> 4) << 4);
    const uint32_t b_lane = (uint32_t)(lane & 7) * (USTR * 2) + (uint32_t)(((lane >> 3) & 1) << 4);
    const uint32_t abase0 = smu + RB_A + (uint32_t)mt * 16 * (HROWP * 2) + a_lane;
    const uint32_t bhib   = smu + RB_U + (uint32_t)nt * 8 * (USTR * 2) + b_lane;
    const uint32_t blob   = bhib + 16 * USTR * 2;

    const int jj = tid & 3;
    const int eb = tid >> 2;
    float creg = 0.0f;
    const int hchunk = j0 >> 8;
    const int hcc    = (j0 & 255);

    for (int t = 0; t < T_STEPS; ++t) {
        if (t > 0) {
            // dual independent accumulator chains (even k -> e, odd k -> f)
            float e0 = 0.f, e1 = 0.f, e2 = 0.f, e3 = 0.f;
            float f0 = 0.f, f1 = 0.f, f2 = 0.f, f3 = 0.f;
            #pragma unroll
            for (int c = 0; c < 2; ++c) {
                if (c == 0) { MBARRIER_WAIT_PARITY(smu + RB_MB0, (t - 1) & 1); }
                else        { MBARRIER_WAIT_PARITY(smu + RB_MB1, (t - 1) & 1); }
                const uint32_t ab = abase0 + (uint32_t)c * ACHUNK_BYTES;
                const uint32_t bofs = (uint32_t)c * 512;
                #pragma unroll
                for (int k = 0; k < 16; k += 2) {
                    uint32_t a0, a1, a2, a3, a4, a5, a6, a7;
                    uint32_t b0, b1, b2, b3;
                    LDMX4(a0, a1, a2, a3, ab + (uint32_t)k * 32);
                    LDMX4(a4, a5, a6, a7, ab + (uint32_t)(k + 1) * 32);
                    LDMX2(b0, b1, bhib + bofs + (uint32_t)k * 32);
                    LDMX2(b2, b3, bhib + bofs + (uint32_t)(k + 1) * 32);
                    MMA16816(e0, e1, e2, e3, a0, a1, a2, a3, b0, b1);
                    MMA16816(f0, f1, f2, f3, a4, a5, a6, a7, b2, b3);
                    LDMX2(b0, b1, blob + bofs + (uint32_t)k * 32);
                    LDMX2(b2, b3, blob + bofs + (uint32_t)(k + 1) * 32);
                    MMA16816(e0, e1, e2, e3, a0, a1, a2, a3, b0, b1);
                    MMA16816(f0, f1, f2, f3, a4, a5, a6, a7, b2, b3);
                }
            }
            {
                int m = mt * 16 + (lane >> 2);
                int n = nt * 8 + 2 * (lane & 3);
                gsm[m * 20 + n]           = e0 + f0;
                gsm[m * 20 + n + 1]       = e1 + f1;
                gsm[(m + 8) * 20 + n]     = e2 + f2;
                gsm[(m + 8) * 20 + n + 1] = e3 + f3;
            }
        }
        __syncthreads();   // gsm visible; ash free; all warps aligned

        if (tid < 256) {
            // ---- compute group: elementwise + publish ----
            if (t > 0) MBARRIER_WAIT_PARITY(smu + RB_MBX, (t - 1) & 1);
            const float* xwb = xwf + (t & 1) * (GR * BATCH);
            float gv[4];
            #pragma unroll
            for (int g = 0; g < 4; ++g) {
                float v = xwb[(g * JCOL + jj) * BATCH + eb];
                if (t > 0) {
                    int n = g * 4 + jj;
                    v += gsm[eb * 20 + n] + gsm[(eb + 64) * 20 + n];
                }
                gv[g] = v;
            }
            float fg = sigmoidf_(gv[0]);
            float ig = sigmoidf_(gv[1]);
            float og = sigmoidf_(gv[2]);
            float cc = tanhfast_(gv[3]);
            float cnew = fg * creg + ig * cc;
            creg = cnew;
            float h = og * tanhfast_(cnew);
            __nv_bfloat16 hi = __float2bfloat16_rn(h);
            __nv_bfloat16 lo = __float2bfloat16_rn(h - __bfloat162float(hi));
            int nb = (t + 1) & 1;
            g_ha[nb][hchunk][eb * HROWP + hcc + jj]        = hi;
            g_ha[nb][hchunk][(eb + 64) * HROWP + hcc + jj] = lo;
            __stcs(hseq + ((size_t)t * BATCH + eb) * HDIM + j0 + jj, h);
            if (t == T_STEPS - 1) {
                hfin[eb * HDIM + j0 + jj] = h;
                cfin[eb * HDIM + j0 + jj] = cnew;
            }
            asm volatile("bar.sync 1, 256;" ::: "memory");   // all h stores done
            if (tid == 0 && t < T_STEPS - 1)
                st_release_gpu(&g_flags[bx * 32], base + (unsigned)(t + 1));
        } else if (t < T_STEPS - 1) {
            // ---- poller group: split flag waits + eager copy issue ----
            const unsigned target = base + (unsigned)(t + 1);
            const int r = tid - 256;
            if (r < 64) {
                while ((int)(ld_acquire_gpu(&g_flags[r * 32]) - target) < 0) { }
                asm volatile("bar.sync 2, 64;" ::: "memory");
                if (r == 0) {
                    MBARRIER_EXPECT_TX(smu + RB_MB0, ACHUNK_BYTES);
                    bulkcp(smu + RB_A, &g_ha[(t + 1) & 1][0][0], ACHUNK_BYTES,
                           smu + RB_MB0);
                }
            } else if (r < 128) {
                while ((int)(ld_acquire_gpu(&g_flags[r * 32]) - target) < 0) { }
                asm volatile("bar.sync 3, 64;" ::: "memory");
                if (r == 64) {
                    MBARRIER_EXPECT_TX(smu + RB_MB1, ACHUNK_BYTES);
                    bulkcp(smu + RB_A + ACHUNK_BYTES, &g_ha[(t + 1) & 1][1][0],
                           ACHUNK_BYTES, smu + RB_MB1);
                    MBARRIER_EXPECT_TX(smu + RB_MBX, XW_BYTES);
                    bulkcp(smu + RB_XW + ((t + 1) & 1) * XW_BYTES,
                           g_xw + ((size_t)(t + 1) * NCTA + bx) * GR * BATCH,
                           XW_BYTES, smu + RB_MBX);
                }
            }
        }
        // no trailing __syncthreads: mbarrier/flag chain orders all reuse
    }
}

extern "C" void kernel_launch(void* const* d_in, const int* in_sizes, int n_in,
                              void* d_out, int out_size)
{
    (void)in_sizes; (void)n_in; (void)out_size;
    const float* x   = (const float*)d_in[0];
    const float* Wf  = (const float*)d_in[1];
    const float* bWf = (const float*)d_in[2];
    const float* Wi  = (const float*)d_in[3];
    const float* bWi = (const float*)d_in[4];
    const float* Wo  = (const float*)d_in[5];
    const float* bWo = (const float*)d_in[6];
    const float* Wc  = (const float*)d_in[7];
    const float* bWc = (const float*)d_in[8];
    const float* Uf  = (const float*)d_in[9];
    const float* bUf = (const float*)d_in[10];
    const float* Ui  = (const float*)d_in[11];
    const float* bUi = (const float*)d_in[12];
    const float* Uo  = (const float*)d_in[13];
    const float* bUo = (const float*)d_in[14];
    const float* Uc  = (const float*)d_in[15];
    const float* bUc = (const float*)d_in[16];

    cudaFuncSetAttribute(lstm_xw_kernel,
                         cudaFuncAttributeMaxDynamicSharedMemorySize, Q_TOTAL);
    cudaFuncSetAttribute(lstm_recur_kernel,
                         cudaFuncAttributeMaxDynamicSharedMemorySize, RB_TOTAL);

    lstm_xcvt_kernel<<<2048, 256>>>(x);

    dim3 g1(32, T_STEPS / P1_TT);
    lstm_xw_kernel<<<g1, NTHR2, Q_TOTAL>>>(
        Wf, bWf, Wi, bWi, Wo, bWo, Wc, bWc, bUf, bUi, bUo, bUc);

    lstm_recur_kernel<<<NCTA, NTHR2, RB_TOTAL>>>(Uf, Ui, Uo, Uc, (float*)d_out);
}

// round 16
// speedup vs baseline: 1.0248x; 1.0248x over previous
#include <cuda_runtime.h>
#include <cuda_bf16.h>
#include <cstdint>

#define T_STEPS 512
#define BATCH   64
#define IDIM    256
#define HDIM    512
#define NCTA    128
#define NTHR2   512
#define JCOL    4
#define GR      16
#define HROWP   264            // bf16 per padded A row (528 B)
#define USTR    520            // bf16 per padded U row, K=512 (1040 B)
#define XROWP   264            // bf16 per padded x-tile row, K=256 (528 B)

typedef unsigned long long ull;

// ---- persistent device scratch ----
__device__ float g_xw[(size_t)T_STEPS * NCTA * GR * BATCH];     // [t][jg][row16][b]
__device__ __nv_bfloat16 g_xa[(size_t)T_STEPS * 128 * XROWP];   // per-t A tiles (hi 0-63, lo 64-127)
__device__ __nv_bfloat16 g_ha[2][2][128 * HROWP];               // [buf][khalf][row128 x HROWP]
__device__ unsigned int g_flags[NCTA * 32];                     // 128B-padded per-CTA flags

// ---------------- helpers ----------------
__device__ __forceinline__ float sigmoidf_(float v) {
    return __fdividef(1.0f, 1.0f + __expf(-v));
}
__device__ __forceinline__ float tanhfast_(float v) {
    return 1.0f - __fdividef(2.0f, __expf(2.0f * v) + 1.0f);
}
__device__ __forceinline__ unsigned ld_acquire_gpu(const unsigned* p) {
    unsigned v;
    asm volatile("ld.acquire.gpu.u32 %0, [%1];" : "=r"(v) : "l"(p) : "memory");
    return v;
}
__device__ __forceinline__ void st_release_gpu(unsigned* p, unsigned v) {
    asm volatile("st.release.gpu.u32 [%0], %1;" :: "l"(p), "r"(v) : "memory");
}
__device__ __forceinline__ uint32_t smem_u32(const void* p) {
    uint32_t a;
    asm("{ .reg .u64 t; cvta.to.shared.u64 t, %1; cvt.u32.u64 %0, t; }" : "=r"(a) : "l"(p));
    return a;
}
__device__ __forceinline__ void bulkcp(uint32_t dst, const void* src, uint32_t bytes,
                                       uint32_t mbar) {
    asm volatile(
        "cp.async.bulk.shared::cluster.global.mbarrier::complete_tx::bytes [%0], [%1], %2, [%3];"
        :: "r"(dst), "l"(src), "r"(bytes), "r"(mbar) : "memory");
}
#define MBARRIER_INIT(mb, c) \
    asm volatile("mbarrier.init.shared.b64 [%0], %1;" :: "r"((uint32_t)(mb)), "r"((uint32_t)(c)) : "memory")
#define MBARRIER_EXPECT_TX(mb, tx) \
    asm volatile("mbarrier.arrive.expect_tx.shared.b64 _, [%0], %1;" \
        :: "r"((uint32_t)(mb)), "r"((uint32_t)(tx)) : "memory")
#define MBARRIER_WAIT_PARITY(mb, par) do {                                            \
    uint32_t _mb = (uint32_t)(mb); uint32_t _p = (uint32_t)(par); uint32_t _done;     \
    asm volatile("{\n\t.reg .pred p;\n\t"                                             \
        "mbarrier.try_wait.parity.acquire.cta.shared::cta.b64 p, [%1], %2;\n\t"       \
        "selp.b32 %0, 1, 0, p;\n\t}" : "=r"(_done) : "r"(_mb), "r"(_p) : "memory");   \
    if (!_done) {                                                                     \
        asm volatile("{\n\t.reg .pred P1;\n\t"                                        \
            "WL_%=:\n\t"                                                              \
            "mbarrier.try_wait.parity.acquire.cta.shared::cta.b64 P1, [%0], %1, 0x989680;\n\t" \
            "@P1 bra.uni WD_%=;\n\t"                                                  \
            "bra.uni WL_%=;\n\t"                                                      \
            "WD_%=:\n\t}" :: "r"(_mb), "r"(_p) : "memory");                           \
    }                                                                                 \
} while (0)

#define LDMX4(r0, r1, r2, r3, addr) \
    asm volatile("ldmatrix.sync.aligned.m8n8.x4.shared.b16 {%0,%1,%2,%3}, [%4];" \
        : "=r"(r0), "=r"(r1), "=r"(r2), "=r"(r3) : "r"(addr))
#define LDMX2(r0, r1, addr) \
    asm volatile("ldmatrix.sync.aligned.m8n8.x2.shared.b16 {%0,%1}, [%2];" \
        : "=r"(r0), "=r"(r1) : "r"(addr))
#define MMA16816(d0, d1, d2, d3, a0, a1, a2, a3, b0, b1) \
    asm volatile("mma.sync.aligned.m16n8k16.row.col.f32.bf16.bf16.f32 " \
        "{%0,%1,%2,%3}, {%4,%5,%6,%7}, {%8,%9}, {%0,%1,%2,%3};" \
        : "+f"(d0), "+f"(d1), "+f"(d2), "+f"(d3) \
        : "r"(a0), "r"(a1), "r"(a2), "r"(a3), "r"(b0), "r"(b1))

// ============================================================================
// Kernel 0: convert x -> g_xa (bf16 hi/lo, padded per-t A tiles)  [R13 verbatim]
// ============================================================================
__global__ void __launch_bounds__(256, 4)
lstm_xcvt_kernel(const float* __restrict__ x)
{
    const int tid = blockIdx.x * 256 + threadIdx.x;
    #pragma unroll
    for (int i = 0; i < 4; ++i) {
        int item = tid + i * 524288;
        int t  = item >> 12;
        int rm = item & 4095;
        int b  = rm >> 6;
        int kq = rm & 63;
        float4 v = __ldg(reinterpret_cast<const float4*>(
            x + ((size_t)t * BATCH + b) * IDIM + kq * 4));
        float h0 = __bfloat162float(__float2bfloat16_rn(v.x));
        float h1 = __bfloat162float(__float2bfloat16_rn(v.y));
        float h2 = __bfloat162float(__float2bfloat16_rn(v.z));
        float h3 = __bfloat162float(__float2bfloat16_rn(v.w));
        uint32_t hp0, hp1, lp0, lp1;
        asm("cvt.rn.bf16x2.f32 %0, %1, %2;" : "=r"(hp0) : "f"(h1), "f"(h0));
        asm("cvt.rn.bf16x2.f32 %0, %1, %2;" : "=r"(hp1) : "f"(h3), "f"(h2));
        asm("cvt.rn.bf16x2.f32 %0, %1, %2;" : "=r"(lp0) : "f"(v.y - h1), "f"(v.x - h0));
        asm("cvt.rn.bf16x2.f32 %0, %1, %2;" : "=r"(lp1) : "f"(v.w - h3), "f"(v.z - h2));
        __nv_bfloat16* dst = g_xa + (size_t)t * 128 * XROWP;
        uint2 hw; hw.x = hp0; hw.y = hp1;
        uint2 lw; lw.x = lp0; lw.y = lp1;
        *reinterpret_cast<uint2*>(dst + b * XROWP + kq * 4) = hw;
        *reinterpret_cast<uint2*>(dst + (b + 64) * XROWP + kq * 4) = lw;
    }
}

// ============================================================================
// Kernel 1: phase-1 mma (double-buffered, gsm overlays dead A buffer) [R13 verbatim]
// ============================================================================
#define P1_TT    32
#define XA_BYTES (128 * XROWP * 2)       // 67584
#define WSTRB    (XROWP * 2)             // 528 B per W row (K=256)

#define Q_MB0   0
#define Q_MB1   8
#define Q_BS    64
#define Q_W     1024
#define Q_A0    68608
#define Q_A1    136192
#define Q_TOTAL 203776

__global__ void __launch_bounds__(NTHR2, 1)
lstm_xw_kernel(const float* __restrict__ Wf, const float* __restrict__ bWf,
               const float* __restrict__ Wi, const float* __restrict__ bWi,
               const float* __restrict__ Wo, const float* __restrict__ bWo,
               const float* __restrict__ Wc, const float* __restrict__ bWc,
               const float* __restrict__ bUf, const float* __restrict__ bUi,
               const float* __restrict__ bUo, const float* __restrict__ bUc)
{
    extern __shared__ char smem[];
    const uint32_t smu = smem_u32(smem);
    float* bsm = (float*)(smem + Q_BS);

    const int tid  = threadIdx.x;
    const int wid  = tid >> 5;
    const int lane = tid & 31;
    const int jg   = blockIdx.x;
    const int t0   = blockIdx.y * P1_TT;
    const int mt   = wid & 7;
    const int ng   = wid >> 3;

    if (tid == 0) {
        MBARRIER_INIT(smu + Q_MB0, 1);
        MBARRIER_INIT(smu + Q_MB1, 1);
    }
    {
        const float* Wg[4]  = {Wf, Wi, Wo, Wc};
        const float* bWg[4] = {bWf, bWi, bWo, bWc};
        const float* bUg[4] = {bUf, bUi, bUo, bUc};
        #pragma unroll 4
        for (int i = 0; i < 32; ++i) {
            int idx = tid + i * NTHR2;
            int row = idx >> 8;
            int k   = idx & 255;
            int gate = (row >> 2) & 3;
            int jcol = jg * 16 + (row >> 4) * 4 + (row & 3);
            float f = Wg[gate][jcol * IDIM + k];
            __nv_bfloat16 hi = __float2bfloat16_rn(f);
            __nv_bfloat16 lo = __float2bfloat16_rn(f - __bfloat162float(hi));
            *(__nv_bfloat16*)(smem + Q_W + row * WSTRB + k * 2) = hi;
            *(__nv_bfloat16*)(smem + Q_W + 64 * WSTRB + row * WSTRB + k * 2) = lo;
        }
        if (tid < 64) {
            int gate = (tid >> 2) & 3;
            int jcol = jg * 16 + (tid >> 4) * 4 + (tid & 3);
            bsm[tid] = (float)(bWg[gate][jcol] + bUg[gate][jcol]);
        }
    }
    __syncthreads();
    if (tid == 0) {
        MBARRIER_EXPECT_TX(smu + Q_MB0, XA_BYTES);
        bulkcp(smu + Q_A0, g_xa + (size_t)t0 * 128 * XROWP, XA_BYTES, smu + Q_MB0);
    }

    const uint32_t a_lane = (uint32_t)(lane & 15) * WSTRB + (uint32_t)((lane >> 4) << 4);
    const uint32_t b_lane = (uint32_t)(lane & 7) * WSTRB + (uint32_t)(((lane >> 3) & 1) << 4);

    for (int tt = 0; tt < P1_TT; ++tt) {
        const int t   = t0 + tt;
        const int cur = tt & 1;
        const uint32_t Acur = smu + (cur ? Q_A1 : Q_A0);

        if (tid == 0 && tt + 1 < P1_TT) {
            const uint32_t mbn = smu + ((tt + 1) & 1 ? Q_MB1 : Q_MB0);
            MBARRIER_EXPECT_TX(mbn, XA_BYTES);
            bulkcp(smu + ((tt + 1) & 1 ? Q_A1 : Q_A0),
                   g_xa + (size_t)(t + 1) * 128 * XROWP, XA_BYTES, mbn);
        }

        MBARRIER_WAIT_PARITY(smu + (cur ? Q_MB1 : Q_MB0), (tt >> 1) & 1);

        float d0[4], d1[4], d2[4], d3[4];
        #pragma unroll
        for (int q = 0; q < 4; ++q) { d0[q] = d1[q] = d2[q] = d3[q] = 0.f; }

        const uint32_t abase = Acur + (uint32_t)mt * 16 * WSTRB + a_lane;
        #pragma unroll
        for (int k = 0; k < 16; ++k) {
            uint32_t a0, a1, a2, a3;
            LDMX4(a0, a1, a2, a3, abase + (uint32_t)k * 32);
            #pragma unroll
            for (int q = 0; q < 4; ++q) {
                uint32_t bh = smu + Q_W + (uint32_t)(ng * 32 + q * 8) * WSTRB + b_lane
                            + (uint32_t)k * 32;
                uint32_t b0, b1;
                LDMX2(b0, b1, bh);
                MMA16816(d0[q], d1[q], d2[q], d3[q], a0, a1, a2, a3, b0, b1);
                LDMX2(b0, b1, bh + 64 * WSTRB);
                MMA16816(d0[q], d1[q], d2[q], d3[q], a0, a1, a2, a3, b0, b1);
            }
        }

        __syncthreads();
        float* gsm = (float*)(smem + (cur ? Q_A1 : Q_A0));
        {
            int m = mt * 16 + (lane >> 2);
            #pragma unroll
            for (int q = 0; q < 4; ++q) {
                int n = ng * 32 + q * 8 + 2 * (lane & 3);
                gsm[m * 66 + n]           = d0[q];
                gsm[m * 66 + n + 1]       = d1[q];
                gsm[(m + 8) * 66 + n]     = d2[q];
                gsm[(m + 8) * 66 + n + 1] = d3[q];
            }
        }
        __syncthreads();
        #pragma unroll
        for (int i = 0; i < 2; ++i) {
            int oidx = tid + i * NTHR2;
            int n  = oidx >> 4;
            int b4 = (oidx & 15) * 4;
            float bb = bsm[n];
            float4 o;
            o.x = gsm[(b4 + 0) * 66 + n] + gsm[(b4 + 64) * 66 + n] + bb;
            o.y = gsm[(b4 + 1) * 66 + n] + gsm[(b4 + 65) * 66 + n] + bb;
            o.z = gsm[(b4 + 2) * 66 + n] + gsm[(b4 + 66) * 66 + n] + bb;
            o.w = gsm[(b4 + 3) * 66 + n] + gsm[(b4 + 67) * 66 + n] + bb;
            size_t row128 = (size_t)t * NCTA + 4 * jg + (n >> 4);
            *reinterpret_cast<float4*>(
                g_xw + (row128 * GR + (n & 15)) * BATCH + b4) = o;
        }
        __syncthreads();
    }
}

// ============================================================================
// Phase 2: 128 CTAs x 4 h-cols, mma.sync; ROW-SPLIT copies (4 mbarriers) so
// each warp waits only for its own 33.8 KB; poller warps + split flags.
// ============================================================================
#define ACHUNK_BYTES (128 * HROWP * 2)        // 67584
#define AHALF_BYTES  (64 * HROWP * 2)         // 33792
#define XW_BYTES     (GR * BATCH * 4)         // 4096

#define RB_MB00  0     // chunk0 (khalf0) hi rows
#define RB_MB01  8     // chunk0 lo rows
#define RB_MB10  16    // chunk1 hi rows
#define RB_MB11  24    // chunk1 lo rows
#define RB_MBX   32
#define RB_EB    40
#define RB_XW    64
#define RB_GSM   (RB_XW + 2 * XW_BYTES)       // 8256; gsm 128*20*4 = 10240
#define RB_U     (RB_GSM + 10240)             // hi 16*1040 + lo 16*1040 = 33280
#define RB_A     (RB_U + 33280)               // 2 * 67584 = 135168
#define RB_TOTAL (RB_A + 2 * ACHUNK_BYTES)    // 186944

__global__ void __launch_bounds__(NTHR2, 1)
lstm_recur_kernel(const float* __restrict__ Uf, const float* __restrict__ Ui,
                  const float* __restrict__ Uo, const float* __restrict__ Uc,
                  float* __restrict__ out)
{
    extern __shared__ char smem[];
    const uint32_t smu = smem_u32(smem);
    float* xwf = (float*)(smem + RB_XW);
    float* gsm = (float*)(smem + RB_GSM);

    const int tid  = threadIdx.x;
    const int wid  = tid >> 5;
    const int lane = tid & 31;
    const int bx   = blockIdx.x;
    const int j0   = bx * JCOL;
    const int mt   = wid & 7;
    const int nt   = wid >> 3;
    const int myhalf = mt >> 2;        // 0: rows 0-63 (hi), 1: rows 64-127 (lo)

    if (tid == 0) {
        MBARRIER_INIT(smu + RB_MB00, 1);
        MBARRIER_INIT(smu + RB_MB01, 1);
        MBARRIER_INIT(smu + RB_MB10, 1);
        MBARRIER_INIT(smu + RB_MB11, 1);
        MBARRIER_INIT(smu + RB_MBX, 1);
        *(unsigned*)(smem + RB_EB) = ld_acquire_gpu(&g_flags[bx * 32]);
    }
    {
        const float* Ug[4] = {Uf, Ui, Uo, Uc};
        for (int i = 0; i < 16; ++i) {
            int idx = tid + i * NTHR2;
            int row = idx >> 9;
            int k   = idx & 511;
            float f = Ug[row >> 2][(j0 + (row & 3)) * HDIM + k];
            __nv_bfloat16 hi = __float2bfloat16_rn(f);
            __nv_bfloat16 lo = __float2bfloat16_rn(f - __bfloat162float(hi));
            *(__nv_bfloat16*)(smem + RB_U + (row * USTR + k) * 2) = hi;
            *(__nv_bfloat16*)(smem + RB_U + 16 * USTR * 2 + (row * USTR + k) * 2) = lo;
        }
        if (tid < 256) {
            const float* src = g_xw + (size_t)bx * GR * BATCH;
            float4 v = __ldg(reinterpret_cast<const float4*>(src + tid * 4));
            *reinterpret_cast<float4*>(xwf + tid * 4) = v;
        }
    }
    __syncthreads();
    const unsigned base = *(unsigned*)(smem + RB_EB);

    float* hseq = out;
    float* hfin = out + (size_t)T_STEPS * BATCH * HDIM;
    float* cfin = hfin + BATCH * HDIM;

    const uint32_t a_lane = (uint32_t)(lane & 15) * (HROWP * 2) + (uint32_t)((lane >> 4) << 4);
    const uint32_t b_lane = (uint32_t)(lane & 7) * (USTR * 2) + (uint32_t)(((lane >> 3) & 1) << 4);
    const uint32_t abase0 = smu + RB_A + (uint32_t)mt * 16 * (HROWP * 2) + a_lane;
    const uint32_t bhib   = smu + RB_U + (uint32_t)nt * 8 * (USTR * 2) + b_lane;
    const uint32_t blob   = bhib + 16 * USTR * 2;
    // barrier offsets for this warp's row-half, per chunk
    const uint32_t mb_c0 = smu + (myhalf ? RB_MB01 : RB_MB00);
    const uint32_t mb_c1 = smu + (myhalf ? RB_MB11 : RB_MB10);

    const int jj = tid & 3;
    const int eb = tid >> 2;
    float creg = 0.0f;
    const int hchunk = j0 >> 8;
    const int hcc    = (j0 & 255);

    for (int t = 0; t < T_STEPS; ++t) {
        if (t > 0) {
            float d0 = 0.f, d1 = 0.f, d2 = 0.f, d3 = 0.f;
            #pragma unroll
            for (int c = 0; c < 2; ++c) {
                MBARRIER_WAIT_PARITY(c == 0 ? mb_c0 : mb_c1, (t - 1) & 1);
                const uint32_t ab = abase0 + (uint32_t)c * ACHUNK_BYTES;
                const uint32_t bofs = (uint32_t)c * 512;
                #pragma unroll
                for (int k = 0; k < 16; ++k) {
                    uint32_t a0, a1, a2, a3, b0, b1;
                    LDMX4(a0, a1, a2, a3, ab + (uint32_t)k * 32);
                    LDMX2(b0, b1, bhib + bofs + (uint32_t)k * 32);
                    MMA16816(d0, d1, d2, d3, a0, a1, a2, a3, b0, b1);
                    LDMX2(b0, b1, blob + bofs + (uint32_t)k * 32);
                    MMA16816(d0, d1, d2, d3, a0, a1, a2, a3, b0, b1);
                }
            }
            {
                int m = mt * 16 + (lane >> 2);
                int n = nt * 8 + 2 * (lane & 3);
                gsm[m * 20 + n]           = d0;
                gsm[m * 20 + n + 1]       = d1;
                gsm[(m + 8) * 20 + n]     = d2;
                gsm[(m + 8) * 20 + n + 1] = d3;
            }
        }
        __syncthreads();   // gsm visible; ash free; all warps aligned

        if (tid < 256) {
            // ---- compute group: elementwise + publish ----
            if (t > 0) MBARRIER_WAIT_PARITY(smu + RB_MBX, (t - 1) & 1);
            const float* xwb = xwf + (t & 1) * (GR * BATCH);
            float gv[4];
            #pragma unroll
            for (int g = 0; g < 4; ++g) {
                float v = xwb[(g * JCOL + jj) * BATCH + eb];
                if (t > 0) {
                    int n = g * 4 + jj;
                    v += gsm[eb * 20 + n] + gsm[(eb + 64) * 20 + n];
                }
                gv[g] = v;
            }
            float fg = sigmoidf_(gv[0]);
            float ig = sigmoidf_(gv[1]);
            float og = sigmoidf_(gv[2]);
            float cc = tanhfast_(gv[3]);
            float cnew = fg * creg + ig * cc;
            creg = cnew;
            float h = og * tanhfast_(cnew);
            __nv_bfloat16 hi = __float2bfloat16_rn(h);
            __nv_bfloat16 lo = __float2bfloat16_rn(h - __bfloat162float(hi));
            int nb = (t + 1) & 1;
            g_ha[nb][hchunk][eb * HROWP + hcc + jj]        = hi;
            g_ha[nb][hchunk][(eb + 64) * HROWP + hcc + jj] = lo;
            __stcs(hseq + ((size_t)t * BATCH + eb) * HDIM + j0 + jj, h);
            if (t == T_STEPS - 1) {
                hfin[eb * HDIM + j0 + jj] = h;
                cfin[eb * HDIM + j0 + jj] = cnew;
            }
            asm volatile("bar.sync 1, 256;" ::: "memory");   // all h stores done
            if (tid == 0 && t < T_STEPS - 1)
                st_release_gpu(&g_flags[bx * 32], base + (unsigned)(t + 1));
        } else if (t < T_STEPS - 1) {
            // ---- poller group: split flag waits + eager row-split copy issue ----
            const unsigned target = base + (unsigned)(t + 1);
            const int r = tid - 256;
            if (r < 64) {
                while ((int)(ld_acquire_gpu(&g_flags[r * 32]) - target) < 0) { }
                asm volatile("bar.sync 2, 64;" ::: "memory");
                if (r == 0) {
                    const __nv_bfloat16* src = &g_ha[(t + 1) & 1][0][0];
                    MBARRIER_EXPECT_TX(smu + RB_MB00, AHALF_BYTES);
                    bulkcp(smu + RB_A, src, AHALF_BYTES, smu + RB_MB00);
                    MBARRIER_EXPECT_TX(smu + RB_MB01, AHALF_BYTES);
                    bulkcp(smu + RB_A + AHALF_BYTES, src + 64 * HROWP,
                           AHALF_BYTES, smu + RB_MB01);
                }
            } else if (r < 128) {
                while ((int)(ld_acquire_gpu(&g_flags[r * 32]) - target) < 0) { }
                asm volatile("bar.sync 3, 64;" ::: "memory");
                if (r == 64) {
                    const __nv_bfloat16* src = &g_ha[(t + 1) & 1][1][0];
                    MBARRIER_EXPECT_TX(smu + RB_MB10, AHALF_BYTES);
                    bulkcp(smu + RB_A + ACHUNK_BYTES, src, AHALF_BYTES,
                           smu + RB_MB10);
                    MBARRIER_EXPECT_TX(smu + RB_MB11, AHALF_BYTES);
                    bulkcp(smu + RB_A + ACHUNK_BYTES + AHALF_BYTES, src + 64 * HROWP,
                           AHALF_BYTES, smu + RB_MB11);
                    MBARRIER_EXPECT_TX(smu + RB_MBX, XW_BYTES);
                    bulkcp(smu + RB_XW + ((t + 1) & 1) * XW_BYTES,
                           g_xw + ((size_t)(t + 1) * NCTA + bx) * GR * BATCH,
                           XW_BYTES, smu + RB_MBX);
                }
            }
        }
        // no trailing __syncthreads: mbarrier/flag chain orders all reuse
    }
}

extern "C" void kernel_launch(void* const* d_in, const int* in_sizes, int n_in,
                              void* d_out, int out_size)
{
    (void)in_sizes; (void)n_in; (void)out_size;
    const float* x   = (const float*)d_in[0];
    const float* Wf  = (const float*)d_in[1];
    const float* bWf = (const float*)d_in[2];
    const float* Wi  = (const float*)d_in[3];
    const float* bWi = (const float*)d_in[4];
    const float* Wo  = (const float*)d_in[5];
    const float* bWo = (const float*)d_in[6];
    const float* Wc  = (const float*)d_in[7];
    const float* bWc = (const float*)d_in[8];
    const float* Uf  = (const float*)d_in[9];
    const float* bUf = (const float*)d_in[10];
    const float* Ui  = (const float*)d_in[11];
    const float* bUi = (const float*)d_in[12];
    const float* Uo  = (const float*)d_in[13];
    const float* bUo = (const float*)d_in[14];
    const float* Uc  = (const float*)d_in[15];
    const float* bUc = (const float*)d_in[16];

    cudaFuncSetAttribute(lstm_xw_kernel,
                         cudaFuncAttributeMaxDynamicSharedMemorySize, Q_TOTAL);
    cudaFuncSetAttribute(lstm_recur_kernel,
                         cudaFuncAttributeMaxDynamicSharedMemorySize, RB_TOTAL);

    lstm_xcvt_kernel<<<2048, 256>>>(x);

    dim3 g1(32, T_STEPS / P1_TT);
    lstm_xw_kernel<<<g1, NTHR2, Q_TOTAL>>>(
        Wf, bWf, Wi, bWi, Wo, bWo, Wc, bWc, bUf, bUi, bUo, bUc);

    lstm_recur_kernel<<<NCTA, NTHR2, RB_TOTAL>>>(Uf, Ui, Uo, Uc, (float*)d_out);
}